// round 1
// baseline (speedup 1.0000x reference)
#include <cuda_runtime.h>

// VPNNetwork: per-sample 48->48 linear (Phi), 20-step value iteration on a 4x4
// grid with 4-neighbor stencil, 3x3 gather around one-hot agent position,
// 36->4 linear (logits).
//
// Inputs (metadata order):
//   d_in[0] obs_flat  [B, 48]   float32
//   d_in[1] Phi_w     [48, 48]  float32
//   d_in[2] Phi_b     [48]      float32
//   d_in[3] Logit_w   [4, 36]   float32
//   d_in[4] Logit_b   [4]       float32
// Output: [B, 4] float32

#define BT       128      // threads per block = samples per block
#define SSTRIDE  129      // padded scratch stride (banks: 128 % 32 == 0 is bad)

__global__ __launch_bounds__(BT) void vpn_kernel(
    const float* __restrict__ obs,
    const float* __restrict__ Pw,
    const float* __restrict__ Pb,
    const float* __restrict__ Lw,
    const float* __restrict__ Lb,
    float* __restrict__ out)
{
    __shared__ __align__(16) float sWt[48 * 48];   // sWt[i*48+o] = Pw[o*48+i]
    __shared__ __align__(16) float sPb[48];
    __shared__ __align__(16) float sLw[36 * 4];    // sLw[k*4+a] = Lw[a*36+k]
    __shared__ __align__(16) float sLb[4];
    __shared__ float scratch[64 * SSTRIDE];        // [cell*4+ch][sample], ch3 = V

    const int tid = threadIdx.x;

    // ---- load + transpose weights into shared ----
    for (int idx = tid; idx < 48 * 48; idx += BT) {
        int o = idx / 48, i = idx - o * 48;
        sWt[i * 48 + o] = Pw[idx];
    }
    if (tid < 48) sPb[tid] = Pb[tid];
    for (int idx = tid; idx < 4 * 36; idx += BT) {
        int a = idx / 36, k = idx - a * 36;
        sLw[k * 4 + a] = Lw[idx];
    }
    if (tid < 4) sLb[tid] = Lb[tid];

    // ---- stage this block's obs into shared scratch (transposed) ----
    // global: sample-major [128][48]; scratch: slot-major [(cell*4+ch)][sample]
    const float4* g4 = reinterpret_cast<const float4*>(
        obs + (size_t)blockIdx.x * BT * 48);
    #pragma unroll
    for (int k = 0; k < 12; k++) {
        int idx4 = tid + k * BT;           // 0..1535
        float4 v4 = g4[idx4];
        int s  = idx4 / 12;                // sample within block
        int e0 = (idx4 - s * 12) * 4;      // first element index (0..44)
        float vv[4] = {v4.x, v4.y, v4.z, v4.w};
        #pragma unroll
        for (int j = 0; j < 4; j++) {
            int e = e0 + j;
            int cell = e / 3;
            int ch = e - cell * 3;
            scratch[(cell * 4 + ch) * SSTRIDE + s] = vv[j];
        }
    }
    __syncthreads();

    // ---- Phi: acc[o] = Phi_b[o] + sum_i x[i] * Pw[o][i] ----
    float acc[48];
    #pragma unroll
    for (int o = 0; o < 48; o++) acc[o] = sPb[o];

    int pos = 0;  // agent cell (exactly one nonzero in ch1)
    #pragma unroll 4
    for (int cellI = 0; cellI < 16; cellI++) {
        #pragma unroll
        for (int ch = 0; ch < 3; ch++) {
            float x = scratch[(cellI * 4 + ch) * SSTRIDE + tid];
            if (ch == 1) { if (x != 0.0f) pos = cellI; }
            const float4* wr = reinterpret_cast<const float4*>(
                sWt + (cellI * 3 + ch) * 48);
            #pragma unroll
            for (int j = 0; j < 12; j++) {
                float4 w = wr[j];
                acc[4 * j + 0] = fmaf(x, w.x, acc[4 * j + 0]);
                acc[4 * j + 1] = fmaf(x, w.y, acc[4 * j + 1]);
                acc[4 * j + 2] = fmaf(x, w.z, acc[4 * j + 2]);
                acc[4 * j + 3] = fmaf(x, w.w, acc[4 * j + 3]);
            }
        }
    }

    // phi layout: rin = acc[c*3+0], rout = acc[c*3+1], p = acc[c*3+2]
    // Precompute step-invariant r[dir][c] = (rin[nb]!=0) ? rin[nb]-rout[c] : 0.
    // dir 0=up(nb=c-4) 1=down(c+4) 2=left(c-1) 3=right(c+1).
    float p_[16], v_[16], rr[4][16];
    #pragma unroll
    for (int c = 0; c < 16; c++) { p_[c] = acc[c * 3 + 2]; v_[c] = 0.0f; }

    #pragma unroll
    for (int h = 0; h < 4; h++) {
        #pragma unroll
        for (int w = 0; w < 4; w++) {
            int c = h * 4 + w;
            float ro = acc[c * 3 + 1];
            if (h > 0) { float rn = acc[(c - 4) * 3]; rr[0][c] = (rn != 0.0f) ? rn - ro : 0.0f; }
            if (h < 3) { float rn = acc[(c + 4) * 3]; rr[1][c] = (rn != 0.0f) ? rn - ro : 0.0f; }
            if (w > 0) { float rn = acc[(c - 1) * 3]; rr[2][c] = (rn != 0.0f) ? rn - ro : 0.0f; }
            if (w < 3) { float rn = acc[(c + 1) * 3]; rr[3][c] = (rn != 0.0f) ? rn - ro : 0.0f; }
        }
    }

    // ---- value iteration, K=20 Jacobi steps ----
    // v >= 0 always, OOB candidates are exactly 0 -> skip them.
    #pragma unroll 4
    for (int k = 0; k < 20; k++) {
        float nv[16];
        #pragma unroll
        for (int h = 0; h < 4; h++) {
            #pragma unroll
            for (int w = 0; w < 4; w++) {
                int c = h * 4 + w;
                float best = v_[c];
                if (h > 0) best = fmaxf(best, fmaf(p_[c], v_[c - 4], rr[0][c]));
                if (h < 3) best = fmaxf(best, fmaf(p_[c], v_[c + 4], rr[1][c]));
                if (w > 0) best = fmaxf(best, fmaf(p_[c], v_[c - 1], rr[2][c]));
                if (w < 3) best = fmaxf(best, fmaf(p_[c], v_[c + 1], rr[3][c]));
                nv[c] = best;
            }
        }
        #pragma unroll
        for (int c = 0; c < 16; c++) v_[c] = nv[c];
    }

    // ---- write V into scratch ch3 (same-thread column, no sync needed) ----
    #pragma unroll
    for (int c = 0; c < 16; c++)
        scratch[(c * 4 + 3) * SSTRIDE + tid] = v_[c];

    // ---- gather 3x3 window around pos, logits = window(36) @ Lw^T + Lb ----
    int ph = pos >> 2, pw = pos & 3;
    float lg0 = sLb[0], lg1 = sLb[1], lg2 = sLb[2], lg3 = sLb[3];
    #pragma unroll
    for (int di = 0; di < 3; di++) {
        int h = ph - 1 + di;
        if ((unsigned)h < 4u) {
            #pragma unroll
            for (int dj = 0; dj < 3; dj++) {
                int w = pw - 1 + dj;
                if ((unsigned)w < 4u) {
                    int c = h * 4 + w;
                    int kbase = (di * 3 + dj) * 4;
                    #pragma unroll
                    for (int ch = 0; ch < 4; ch++) {
                        float val = scratch[(c * 4 + ch) * SSTRIDE + tid];
                        float4 lw = *reinterpret_cast<const float4*>(
                            sLw + (kbase + ch) * 4);
                        lg0 = fmaf(val, lw.x, lg0);
                        lg1 = fmaf(val, lw.y, lg1);
                        lg2 = fmaf(val, lw.z, lg2);
                        lg3 = fmaf(val, lw.w, lg3);
                    }
                }
            }
        }
    }

    reinterpret_cast<float4*>(out)[blockIdx.x * BT + tid] =
        make_float4(lg0, lg1, lg2, lg3);
}

extern "C" void kernel_launch(void* const* d_in, const int* in_sizes, int n_in,
                              void* d_out, int out_size)
{
    const float* obs = (const float*)d_in[0];
    const float* Pw  = (const float*)d_in[1];
    const float* Pb  = (const float*)d_in[2];
    const float* Lw  = (const float*)d_in[3];
    const float* Lb  = (const float*)d_in[4];
    float* out = (float*)d_out;

    int B = in_sizes[0] / 48;          // 262144
    int grid = B / BT;                 // 2048 (B divisible by 128 for this problem)
    vpn_kernel<<<grid, BT>>>(obs, Pw, Pb, Lw, Lb, out);
}